// round 16
// baseline (speedup 1.0000x reference)
#include <cuda_runtime.h>

// ---------------------------------------------------------------------------
// CumulantSOAP, fused: row-major streaming phase 1 (82% DRAM) + L2-resident
// partials (__ldcs on X) + last-64-arriver fold tail.
//   phase 1 (592 blocks, 4/SM all-resident): thread = 4 cols of full P,
//     rows strided G -> g_partial[m][b][col] (12 MB, L2-resident since X is
//     loaded evict-first).
//   fold   (last 64 arrival tickets; one spin on g_arr==592): slot ->
//     (way y, stripe cs); fold 74 partials for 128 cols -> g_mid[m][y][col].
//   finish (per-stripe last of 8, continuation): fold 8 ways, fp32 cumulants,
//     (c - mu) @ W slice -> g_outp[cs][8].
//   final  (last of 8, continuation): sum outputs -> out, reset counters.
// Deterministic: fixed j-ranges and summation order at every level (executor
// identity never affects the computation). Deadlock-free: single spin on a
// counter all 592 co-resident blocks increment unconditionally first.
// ---------------------------------------------------------------------------

#define NM    5
#define GTOT  592        // 148 SMs x 4 blocks, all resident
#define PMAX  1024
#define NWAY  8
#define FCH   (GTOT / NWAY)   // 74 partials per way

__device__ float g_partial[NM * GTOT * PMAX];    // [m][b][col]  (12 MB)
__device__ float g_mid[NM * NWAY * PMAX];        // [m][y][col]  (160 KB)
__device__ float g_outp[8 * 8];                  // per-stripe outputs
__device__ float g_cum[NM * PMAX];               // generic-fallback only
__device__ unsigned g_arr = 0;                   // phase-1 arrival tickets
__device__ unsigned g_cs[8];                     // per-stripe fold tickets
__device__ unsigned g_fin = 0;                   // finisher tickets

// ---- packed f32x2 helpers (Blackwell FFMA2 path, PTX-only) ----------------
static __device__ __forceinline__ unsigned long long f2_mul(unsigned long long a,
                                                            unsigned long long b) {
    unsigned long long d;
    asm("mul.rn.f32x2 %0, %1, %2;" : "=l"(d) : "l"(a), "l"(b));
    return d;
}
static __device__ __forceinline__ unsigned long long f2_add(unsigned long long a,
                                                            unsigned long long b) {
    unsigned long long d;
    asm("add.rn.f32x2 %0, %1, %2;" : "=l"(d) : "l"(a), "l"(b));
    return d;
}
static __device__ __forceinline__ unsigned long long f2_fma(unsigned long long a,
                                                            unsigned long long b,
                                                            unsigned long long c) {
    unsigned long long d;
    asm("fma.rn.f32x2 %0, %1, %2, %3;" : "=l"(d) : "l"(a), "l"(b), "l"(c));
    return d;
}
static __device__ __forceinline__ float2 f2_unpack(unsigned long long v) {
    float2 f;
    asm("mov.b64 {%0, %1}, %2;" : "=f"(f.x), "=f"(f.y) : "l"(v));
    return f;
}

#define ACC(u, s1, s2, s3, s4, s5)                         \
    do {                                                   \
        unsigned long long _x2 = f2_mul((u), (u));         \
        unsigned long long _x3 = f2_mul(_x2, (u));         \
        (s1) = f2_add((s1), (u));                          \
        (s2) = f2_fma((u), (u), (s2));                     \
        (s3) = f2_fma(_x2, (u), (s3));                     \
        (s4) = f2_fma(_x2, _x2, (s4));                     \
        (s5) = f2_fma(_x3, _x2, (s5));                     \
    } while (0)

// ---------------------------------------------------------------------------
__global__ __launch_bounds__(256, 4)
void k_fused(const float* __restrict__ X, const float* __restrict__ mu,
             const float* __restrict__ W, float* __restrict__ out, int N) {
    const int b   = blockIdx.x;
    const int tid = threadIdx.x;
    const int P = PMAX;
    const int G = GTOT;

    __shared__ float s_buf[NM * 8 * 32 * 4]; // 20 KB fold scratch (float4 grid)
    __shared__ float s_cm[NM * 128];         // cumulants - mu (finish)
    __shared__ unsigned s_tkt;

    // ================= phase 1: streaming raw moments (row-major) ==========
    {
        const int col4 = tid * 4;
        unsigned long long s1a = 0ULL, s2a = 0ULL, s3a = 0ULL, s4a = 0ULL, s5a = 0ULL;
        unsigned long long s1b = 0ULL, s2b = 0ULL, s3b = 0ULL, s4b = 0ULL, s5b = 0ULL;

        const char* base = (const char*)(X + col4);
        const size_t rowBytes = (size_t)P * sizeof(float);

        int r = b;
        const int G4 = 4 * G;
        for (; r + 3 * G < N; r += G4) {
            ulonglong2 v0 = __ldcs((const ulonglong2*)(base + (size_t)r * rowBytes));
            ulonglong2 v1 = __ldcs((const ulonglong2*)(base + (size_t)(r + G) * rowBytes));
            ulonglong2 v2 = __ldcs((const ulonglong2*)(base + (size_t)(r + 2 * G) * rowBytes));
            ulonglong2 v3 = __ldcs((const ulonglong2*)(base + (size_t)(r + 3 * G) * rowBytes));
            ACC(v0.x, s1a, s2a, s3a, s4a, s5a);
            ACC(v0.y, s1b, s2b, s3b, s4b, s5b);
            ACC(v1.x, s1a, s2a, s3a, s4a, s5a);
            ACC(v1.y, s1b, s2b, s3b, s4b, s5b);
            ACC(v2.x, s1a, s2a, s3a, s4a, s5a);
            ACC(v2.y, s1b, s2b, s3b, s4b, s5b);
            ACC(v3.x, s1a, s2a, s3a, s4a, s5a);
            ACC(v3.y, s1b, s2b, s3b, s4b, s5b);
        }
        for (; r < N; r += G) {
            ulonglong2 v = __ldcs((const ulonglong2*)(base + (size_t)r * rowBytes));
            ACC(v.x, s1a, s2a, s3a, s4a, s5a);
            ACC(v.y, s1b, s2b, s3b, s4b, s5b);
        }

        const size_t GP = (size_t)G * P;
        float* o = g_partial + (size_t)b * P + col4;
        float2 a, bb;
        a = f2_unpack(s1a); bb = f2_unpack(s1b);
        *(float4*)(o + 0 * GP) = make_float4(a.x, a.y, bb.x, bb.y);
        a = f2_unpack(s2a); bb = f2_unpack(s2b);
        *(float4*)(o + 1 * GP) = make_float4(a.x, a.y, bb.x, bb.y);
        a = f2_unpack(s3a); bb = f2_unpack(s3b);
        *(float4*)(o + 2 * GP) = make_float4(a.x, a.y, bb.x, bb.y);
        a = f2_unpack(s4a); bb = f2_unpack(s4b);
        *(float4*)(o + 3 * GP) = make_float4(a.x, a.y, bb.x, bb.y);
        a = f2_unpack(s5a); bb = f2_unpack(s5b);
        *(float4*)(o + 4 * GP) = make_float4(a.x, a.y, bb.x, bb.y);
    }

    // ================= arrival ticket =================
    __threadfence();
    __syncthreads();
    if (tid == 0) s_tkt = atomicAdd(&g_arr, 1u);
    __syncthreads();
    const unsigned tkt = s_tkt;
    if (tkt < (unsigned)(GTOT - 64)) return;   // last 64 arrivers continue

    const int slot = (int)tkt - (GTOT - 64);   // 0..63
    const int y  = slot >> 3;                  // way 0..7
    const int cs = slot & 7;                   // stripe 0..7

    // single spin: wait for ALL phase-1 arrivals (we already incremented)
    if (tid == 0) {
        while (*(volatile unsigned*)&g_arr < (unsigned)GTOT) __nanosleep(64);
    }
    __syncthreads();
    __threadfence();

    // ================= fold: way y of stripe cs (74 partials, L2-hot) ======
    {
        const int q = tid & 31;                // col-quad within stripe
        const int s = tid >> 5;                // sub-way 0..7
        const size_t GP = (size_t)GTOT * PMAX;
        const int colq = cs * 128 + q * 4;

        float4 acc[NM];
#pragma unroll
        for (int m = 0; m < NM; m++) acc[m] = make_float4(0.f, 0.f, 0.f, 0.f);

        const int j0 = y * FCH;
        const int j1 = j0 + FCH;
        for (int j = j0 + s; j < j1; j += 8) {
            const size_t off = (size_t)j * PMAX + colq;
#pragma unroll
            for (int m = 0; m < NM; m++) {
                const float4 v = *(const float4*)(g_partial + (size_t)m * GP + off);
                acc[m].x += v.x; acc[m].y += v.y; acc[m].z += v.z; acc[m].w += v.w;
            }
        }

        // smem combine: [m][s][q] float4
#pragma unroll
        for (int m = 0; m < NM; m++)
            *(float4*)&s_buf[((m * 8 + s) * 32 + q) * 4] = acc[m];
        __syncthreads();

        if (s == 0) {
#pragma unroll
            for (int m = 0; m < NM; m++) {
                float4 v = make_float4(0.f, 0.f, 0.f, 0.f);
#pragma unroll
                for (int j = 0; j < 8; j++) {
                    const float4 u = *(const float4*)&s_buf[((m * 8 + j) * 32 + q) * 4];
                    v.x += u.x; v.y += u.y; v.z += u.z; v.w += u.w;
                }
                *(float4*)&g_mid[(size_t)m * (NWAY * PMAX) + (size_t)y * PMAX + colq] = v;
            }
        }
    }

    __threadfence();
    __syncthreads();
    if (tid == 0) s_tkt = atomicAdd(&g_cs[cs], 1u);
    __syncthreads();
    if (s_tkt != NWAY - 1) return;             // per-stripe LAST folder continues

    // ================= finish: stripe cs (128 cols) =========================
    __threadfence();                            // acquire all 8 ways

    if (tid < 128) {
        const int lc = tid;
        const int col = cs * 128 + lc;
        float t[NM];
#pragma unroll
        for (int m = 0; m < NM; m++) {
            float v = 0.f;
#pragma unroll
            for (int j = 0; j < NWAY; j++)
                v += g_mid[(size_t)m * (NWAY * PMAX) + (size_t)j * PMAX + col];
            t[m] = v;
        }
        const float invN = 1.0f / (float)N;
        const float m1 = t[0] * invN;
        const float r2 = t[1] * invN;
        const float r3 = t[2] * invN;
        const float r4 = t[3] * invN;
        const float r5 = t[4] * invN;
        const float m2 = m1 * m1;
        const float m3 = m2 * m1;

        const float mu2 = r2 - m2;
        const float mu3 = r3 - 3.0f * m1 * r2 + 2.0f * m3;
        const float mu5 = r5 - 5.0f * m1 * r4 + 10.0f * m2 * r3 - 10.0f * m3 * r2
                          + 4.0f * m3 * m2;

        const float* mup = mu + (size_t)col * NM;    // unaligned: scalars
        s_cm[0 * 128 + lc] = m1                        - __ldg(&mup[0]);
        s_cm[1 * 128 + lc] = 0.f                       - __ldg(&mup[1]);
        s_cm[2 * 128 + lc] = mu2                       - __ldg(&mup[2]);
        s_cm[3 * 128 + lc] = (mu3 - 3.0f * mu2 * mu2)  - __ldg(&mup[3]);
        s_cm[4 * 128 + lc] = (mu5 - 10.0f * mu2 * mu3) - __ldg(&mup[4]);
    }
    __syncthreads();

    // projection: warp p -> output k=p over this stripe's 128 cols
    {
        const int p = tid >> 5;                 // 0..7
        const int l = tid & 31;
        float a = 0.f;
#pragma unroll
        for (int g4 = 0; g4 < 4; g4++) {
            const int lc = l + g4 * 32;
            const int col = cs * 128 + lc;
#pragma unroll
            for (int q = 0; q < NM; q++)
                a += s_cm[q * 128 + lc] * __ldg(&W[(size_t)col * 40 + q * 8 + p]);
        }
#pragma unroll
        for (int o = 16; o > 0; o >>= 1)
            a += __shfl_down_sync(0xffffffffu, a, o);
        if (l == 0) g_outp[cs * 8 + p] = a;
    }

    __threadfence();
    __syncthreads();
    if (tid == 0) s_tkt = atomicAdd(&g_fin, 1u);
    __syncthreads();
    if (s_tkt != 7) return;                     // LAST stripe finisher remains

    // ================= final: sum 8 partial outputs + reset ================
    __threadfence();
    if (tid < 8) {
        float v = 0.f;
#pragma unroll
        for (int i = 0; i < 8; i++) v += g_outp[i * 8 + tid];
        out[tid] = v;
    }
    if (tid < 8) g_cs[tid] = 0;
    if (tid == 0) { g_arr = 0; g_fin = 0; }
    __threadfence();
}

// ---------------------------------------------------------------------------
// Generic fallback path (K != 8 or P != 1024): 3 separate kernels, fp32.
// ---------------------------------------------------------------------------
__global__ __launch_bounds__(256, 4)
void k_moments(const float* __restrict__ X, int N, int P, int G) {
    const int b = blockIdx.x;
    const int tid = threadIdx.x;
    const int col4 = tid * 4;

    unsigned long long s1a = 0ULL, s2a = 0ULL, s3a = 0ULL, s4a = 0ULL, s5a = 0ULL;
    unsigned long long s1b = 0ULL, s2b = 0ULL, s3b = 0ULL, s4b = 0ULL, s5b = 0ULL;

    const char* base = (const char*)(X + col4);
    const size_t rowBytes = (size_t)P * sizeof(float);

    for (int r = b; r < N; r += G) {
        ulonglong2 v = __ldcs((const ulonglong2*)(base + (size_t)r * rowBytes));
        ACC(v.x, s1a, s2a, s3a, s4a, s5a);
        ACC(v.y, s1b, s2b, s3b, s4b, s5b);
    }

    const size_t GP = (size_t)G * P;
    float* o = g_partial + (size_t)b * P + col4;
    float2 a, bb;
    a = f2_unpack(s1a); bb = f2_unpack(s1b);
    *(float4*)(o + 0 * GP) = make_float4(a.x, a.y, bb.x, bb.y);
    a = f2_unpack(s2a); bb = f2_unpack(s2b);
    *(float4*)(o + 1 * GP) = make_float4(a.x, a.y, bb.x, bb.y);
    a = f2_unpack(s3a); bb = f2_unpack(s3b);
    *(float4*)(o + 2 * GP) = make_float4(a.x, a.y, bb.x, bb.y);
    a = f2_unpack(s4a); bb = f2_unpack(s4b);
    *(float4*)(o + 3 * GP) = make_float4(a.x, a.y, bb.x, bb.y);
    a = f2_unpack(s5a); bb = f2_unpack(s5b);
    *(float4*)(o + 4 * GP) = make_float4(a.x, a.y, bb.x, bb.y);
}

__global__ __launch_bounds__(128)
void k_reduceB_gen(const float* __restrict__ mu, int N, int P, int G) {
    const int col = blockIdx.x * 128 + threadIdx.x;
    if (col >= P) return;
    const size_t GP = (size_t)G * P;

    float t[NM] = {0.f, 0.f, 0.f, 0.f, 0.f};
    for (int bb = 0; bb < G; bb++) {
#pragma unroll
        for (int m = 0; m < NM; m++)
            t[m] += g_partial[(size_t)m * GP + (size_t)bb * P + col];
    }

    const float invN = 1.0f / (float)N;
    const float m1 = t[0] * invN;
    const float r2 = t[1] * invN;
    const float r3 = t[2] * invN;
    const float r4 = t[3] * invN;
    const float r5 = t[4] * invN;
    const float m2 = m1 * m1;
    const float m3 = m2 * m1;

    const float mu2 = r2 - m2;
    const float mu3 = r3 - 3.0f * m1 * r2 + 2.0f * m3;
    const float mu5 = r5 - 5.0f * m1 * r4 + 10.0f * m2 * r3 - 10.0f * m3 * r2
                      + 4.0f * m3 * m2;

    const int j = col * NM;
    g_cum[j + 0] = m1 - mu[j + 0];
    g_cum[j + 1] = 0.f - mu[j + 1];
    g_cum[j + 2] = mu2 - mu[j + 2];
    g_cum[j + 3] = (mu3 - 3.0f * mu2 * mu2) - mu[j + 3];
    g_cum[j + 4] = (mu5 - 10.0f * mu2 * mu3) - mu[j + 4];
}

__global__ void k_project_gen(const float* __restrict__ W, float* __restrict__ out,
                              int P5, int K) {
    const int w = blockIdx.x;
    const int lane = threadIdx.x;
    float acc = 0.f;
    for (int i = lane; i < P5; i += 32)
        acc += g_cum[i] * W[(size_t)i * K + w];
#pragma unroll
    for (int o = 16; o > 0; o >>= 1)
        acc += __shfl_down_sync(0xffffffffu, acc, o);
    if (lane == 0) out[w] = acc;
}

// ---------------------------------------------------------------------------
extern "C" void kernel_launch(void* const* d_in, const int* in_sizes, int n_in,
                              void* d_out, int out_size) {
    const float* X  = (const float*)d_in[0];
    const float* mu = (const float*)d_in[1];
    const float* W  = (const float*)d_in[2];
    float* out = (float*)d_out;

    const int P5 = in_sizes[1];          // P * 5
    const int P  = P5 / NM;              // 1024
    const int N  = in_sizes[0] / P;      // 100000
    const int K  = in_sizes[2] / P5;     // 8

    if (K == 8 && P == 1024) {
        k_fused<<<GTOT, 256>>>(X, mu, W, out, N);
    } else {
        const int Gg = GTOT;
        k_moments<<<Gg, P / 4>>>(X, N, P, Gg);
        k_reduceB_gen<<<(P + 127) / 128, 128>>>(mu, N, P, Gg);
        k_project_gen<<<K, 32>>>(W, out, P5, K);
    }
}